// round 14
// baseline (speedup 1.0000x reference)
#include <cuda_runtime.h>
#include <cuda_bf16.h>
#include <math.h>

#define Hh   8
#define Dm   128
#define Ee   128
#define KDk  16
#define Bb   16
#define NPICK 250
#define NDEL  250
#define Gg   501            // 1 + NPICK + NDEL
#define NTOK (Bb*Gg)        // 8016
#define NTOKP 8064          // padded token count (64-token tiles)

typedef unsigned long long u64;

// ---------------- packed f32x2 helpers (FFMA2 path, 2x fp32 rate) ----------
__device__ __forceinline__ u64 fma2(u64 a, u64 b, u64 c) {
    u64 d; asm("fma.rn.f32x2 %0, %1, %2, %3;" : "=l"(d) : "l"(a), "l"(b), "l"(c));
    return d;
}
__device__ __forceinline__ u64 mul2(u64 a, u64 b) {
    u64 d; asm("mul.rn.f32x2 %0, %1, %2;" : "=l"(d) : "l"(a), "l"(b));
    return d;
}
__device__ __forceinline__ u64 add2(u64 a, u64 b) {
    u64 d; asm("add.rn.f32x2 %0, %1, %2;" : "=l"(d) : "l"(a), "l"(b));
    return d;
}
__device__ __forceinline__ void upk(u64 a, float& x, float& y) {
    asm("mov.b64 {%0, %1}, %2;" : "=f"(x), "=f"(y) : "l"(a));
}
__device__ __forceinline__ u64 dup2(float x) {
    u64 r; asm("mov.b64 %0, {%1, %1};" : "=l"(r) : "f"(x));
    return r;
}
__device__ __forceinline__ float ex2f(float x) {
    float r; asm("ex2.approx.ftz.f32 %0, %1;" : "=f"(r) : "f"(x));
    return r;
}

union F4 { float4 v; u64 p[2]; };

// ---------------- device scratch ----------------
#define WPAD 132
__device__ float g_Wt[Hh*7*KDk*WPAD];       // transposed+padded weights
__device__ float g_K [Hh*Bb*Gg*KDk];
__device__ float g_V [Hh*Bb*Gg*KDk];
__device__ float g_Qm[Hh*Bb*Gg*KDk];        // pre-scaled by nf*log2(e)
__device__ float g_QA[Hh*Bb*Gg*KDk];
__device__ float g_QB[Hh*Bb*Gg*KDk];
__device__ float g_heads3[NTOKP*128];       // token-major heads [token][h*16+v]

#define SCL   (0.25f * 1.44269504f)    // 1/sqrt(KD) * log2(e)
#define M2OFF 16.0f                    // fixed softmax offset (log2 units)

// ==========================================================================
// Kernel 0: weight prep.  g_Wt[h][m*16+k][d] = W_m[h][d][k]  (row pad 132)
// ==========================================================================
__global__ void wprep_kernel(const float* __restrict__ Wq, const float* __restrict__ Wk,
                             const float* __restrict__ Wv, const float* __restrict__ W1,
                             const float* __restrict__ W2, const float* __restrict__ W3,
                             const float* __restrict__ W4)
{
    const float* Ws[7] = {Wq, Wk, Wv, W1, W2, W3, W4};
    const int m = blockIdx.x, h = blockIdx.y;
    const float* w = Ws[m] + h * (Dm*KDk);
    float* dst = g_Wt + (size_t)(h*7*KDk + m*KDk) * WPAD;
    for (int idx = threadIdx.x; idx < Dm*KDk; idx += 256) {
        int d = idx >> 4, k = idx & 15;
        dst[k*WPAD + d] = w[idx];
    }
}

// ==========================================================================
// Kernel 1: projections — PERSISTENT PER HEAD.  Grid (19, 8) = 152 blocks,
// 256 threads.  Weights staged ONCE per block; loop over ~5.3 q-chunks.
// thread (k = tid&15, tg = tid>>4): 5 tokens x 7 mats, fma2 inner loop.
// ==========================================================================
#define PT_TOK 80
#define NCHUNK ((NTOK + PT_TOK - 1)/PT_TOK)   // 101
#define PB     19
#define QPAD   132
#define K1_SMEM ((7*16*WPAD + PT_TOK*QPAD)*4)   // 101376 B

__global__ void __launch_bounds__(256) proj_kernel(const float* __restrict__ q)
{
    extern __shared__ float sm[];
    float* Wt = sm;                         // 112*132
    float* qs = sm + 7*KDk*WPAD;            // 80*132

    const int h   = blockIdx.y;
    const int tid = threadIdx.x;

    {   // stage padded weights ONCE (contiguous float2 copy, L2-hot)
        const float2* src = (const float2*)(g_Wt + (size_t)h*7*KDk*WPAD);
        float2*       dst = (float2*)Wt;
#pragma unroll
        for (int i = 0; i < 29; i++) {      // 29*256 = 7424 >= 7392
            int idx = tid + i*256;
            if (idx < 7*KDk*WPAD/2) dst[idx] = src[idx];
        }
    }

    const int k  = tid & 15;
    const int tg = tid >> 4;                // 16 groups x 5 tokens
    const int t0 = tg * 5;

    const float4* wr[7];
#pragma unroll
    for (int m = 0; m < 7; m++) wr[m] = (const float4*)(Wt + (m*16 + k)*WPAD);

    for (int c = blockIdx.x; c < NCHUNK; c += PB) {
        const int base = c * PT_TOK;
        const int nTok = min(PT_TOK, NTOK - base);

        __syncthreads();    // protect qs from previous iteration's readers
        {   // stage q rows with padding (float4 granularity)
            const float4* qg = (const float4*)(q + (size_t)base * Dm);
            const int n4 = nTok * (Dm/4);
            for (int idx = tid; idx < n4; idx += 256) {
                int t = idx >> 5, i = idx & 31;
                ((float4*)(qs + t*QPAD))[i] = qg[idx];
            }
        }
        __syncthreads();

        u64 acc[5][7];
#pragma unroll
        for (int i = 0; i < 5; i++)
#pragma unroll
            for (int m = 0; m < 7; m++) acc[i][m] = 0ull;

        const float4* qr[5];
#pragma unroll
        for (int i = 0; i < 5; i++) qr[i] = (const float4*)(qs + (t0 + i)*QPAD);

#pragma unroll 2
        for (int d4 = 0; d4 < Dm/4; d4++) {
            F4 qv[5];
#pragma unroll
            for (int i = 0; i < 5; i++) qv[i].v = qr[i][d4];
#pragma unroll
            for (int m = 0; m < 7; m++) {
                F4 w; w.v = wr[m][d4];
#pragma unroll
                for (int i = 0; i < 5; i++) {
                    acc[i][m] = fma2(qv[i].p[0], w.p[0], acc[i][m]);
                    acc[i][m] = fma2(qv[i].p[1], w.p[1], acc[i][m]);
                }
            }
        }

#pragma unroll
        for (int i = 0; i < 5; i++) {
            if (t0 + i >= nTok) break;
            float s[7];
#pragma unroll
            for (int m = 0; m < 7; m++) { float x, y; upk(acc[i][m], x, y); s[m] = x + y; }
            const int token = base + t0 + i;
            const int b = token / Gg;
            const int g = token - b * Gg;
            const bool pick = (g >= 1 && g <= NPICK);
            const int idx = ((h*Bb + b)*Gg + g)*KDk + k;
            g_Qm[idx] = s[0] * SCL;
            g_K [idx] = s[1];
            g_V [idx] = s[2];
            g_QA[idx] = (pick ? s[3] : s[5]) * SCL;
            g_QB[idx] = (pick ? s[4] : s[6]) * SCL;
        }
    }
}

// ==========================================================================
// Kernel 2: fused attention (round-9 config; token-major output writes).
// Block = (b,h): 128 blocks x 256 threads, TWO q-rows per thread.
// ==========================================================================
#define K2_SMEM (2*Gg*KDk*4)   // 64128 B

template<bool ZMASK>
__device__ __forceinline__ void attn_scan2(const u64* __restrict__ q0,
                                           const u64* __restrict__ q1,
                                           const float4* __restrict__ Kb,
                                           const float4* __restrict__ Vb,
                                           int n,
                                           float& l0, float& l1,
                                           u64* __restrict__ o0,
                                           u64* __restrict__ o1)
{
#pragma unroll 2
    for (int g = 0; g < n; g++) {
        F4 k0, k1, k2, k3;
        k0.v = Kb[g*4+0]; k1.v = Kb[g*4+1];
        k2.v = Kb[g*4+2]; k3.v = Kb[g*4+3];

        u64 a0 = mul2(q0[0], k0.p[0]);
        u64 a1 = mul2(q0[1], k0.p[1]);
        u64 c0 = mul2(q1[0], k0.p[0]);
        u64 c1 = mul2(q1[1], k0.p[1]);
        a0 = fma2(q0[2], k1.p[0], a0);
        a1 = fma2(q0[3], k1.p[1], a1);
        c0 = fma2(q1[2], k1.p[0], c0);
        c1 = fma2(q1[3], k1.p[1], c1);
        a0 = fma2(q0[4], k2.p[0], a0);
        a1 = fma2(q0[5], k2.p[1], a1);
        c0 = fma2(q1[4], k2.p[0], c0);
        c1 = fma2(q1[5], k2.p[1], c1);
        a0 = fma2(q0[6], k3.p[0], a0);
        a1 = fma2(q0[7], k3.p[1], a1);
        c0 = fma2(q1[6], k3.p[0], c0);
        c1 = fma2(q1[7], k3.p[1], c1);
        a0 = add2(a0, a1);
        c0 = add2(c0, c1);

        // V loads issued before the MUFU so LDS latency overlaps exp
        F4 v0, v1, v2, v3;
        v0.v = Vb[g*4+0]; v1.v = Vb[g*4+1];
        v2.v = Vb[g*4+2]; v3.v = Vb[g*4+3];

        float x, y;
        upk(a0, x, y); float s0 = x + y;
        upk(c0, x, y); float s1 = x + y;
        float p0 = ex2f(s0 - M2OFF);
        float p1 = ex2f(s1 - M2OFF);
        if (ZMASK) {                       // zmask: score==0 -> excluded
            p0 = (s0 == 0.f) ? 0.f : p0;
            p1 = (s1 == 0.f) ? 0.f : p1;
        }
        l0 += p0;
        l1 += p1;
        u64 pp0 = dup2(p0), pp1 = dup2(p1);
        o0[0] = fma2(pp0, v0.p[0], o0[0]);
        o1[0] = fma2(pp1, v0.p[0], o1[0]);
        o0[1] = fma2(pp0, v0.p[1], o0[1]);
        o1[1] = fma2(pp1, v0.p[1], o1[1]);
        o0[2] = fma2(pp0, v1.p[0], o0[2]);
        o1[2] = fma2(pp1, v1.p[0], o1[2]);
        o0[3] = fma2(pp0, v1.p[1], o0[3]);
        o1[3] = fma2(pp1, v1.p[1], o1[3]);
        o0[4] = fma2(pp0, v2.p[0], o0[4]);
        o1[4] = fma2(pp1, v2.p[0], o1[4]);
        o0[5] = fma2(pp0, v2.p[1], o0[5]);
        o1[5] = fma2(pp1, v2.p[1], o1[5]);
        o0[6] = fma2(pp0, v3.p[0], o0[6]);
        o1[6] = fma2(pp1, v3.p[0], o1[6]);
        o0[7] = fma2(pp0, v3.p[1], o0[7]);
        o1[7] = fma2(pp1, v3.p[1], o1[7]);
    }
}

__global__ void __launch_bounds__(256) attn_kernel()
{
    extern __shared__ float sm[];

    const int b  = blockIdx.x;
    const int h  = blockIdx.y;
    const int tid = threadIdx.x;
    const int hb  = h*Bb + b;

    {   // stage K,V for this (h,b): 501 x 16 floats each
        const float4* Kg = (const float4*)(g_K + (size_t)hb * Gg * KDk);
        const float4* Vg = (const float4*)(g_V + (size_t)hb * Gg * KDk);
        float4* Ks4 = (float4*)sm;
        float4* Vs4 = (float4*)(sm + Gg*KDk);
        for (int i = tid; i < Gg*4; i += 256) { Ks4[i] = Kg[i]; Vs4[i] = Vg[i]; }
    }
    __syncthreads();

    const float4* Ks = (const float4*)sm;
    const float4* Vs = Ks + Gg*4;

    const int r0 = tid;                         // always < 501
    const bool has1 = (tid + 256 < Gg);
    const int r1 = has1 ? (tid + 256) : (Gg - 1);   // clamped; output guarded

    const int qi0 = (hb*Gg + r0)*KDk;
    const int qi1 = (hb*Gg + r1)*KDk;

    float l0 = 0.f, l1 = 0.f;
    u64 o0[8], o1[8];
#pragma unroll
    for (int j = 0; j < 8; j++) { o0[j] = 0ull; o1[j] = 0ull; }

    {   // ---- main block: 501 keys, no mask ----
        u64 q0[8], q1[8];
        const u64* p0 = (const u64*)(g_Qm + qi0);
        const u64* p1 = (const u64*)(g_Qm + qi1);
#pragma unroll
        for (int j = 0; j < 8; j++) { q0[j] = p0[j]; q1[j] = p1[j]; }
        attn_scan2<false>(q0, q1, Ks, Vs, Gg, l0, l1, o0, o1);
    }

    {   // ---- extra blocks; row 0 gets zeroed Q -> s==0 -> masked out ----
        const bool z0 = (r0 == 0);
        u64 q0[8], q1[8];
        {
            const u64* p0 = (const u64*)(g_QA + qi0);
            const u64* p1 = (const u64*)(g_QA + qi1);
#pragma unroll
            for (int j = 0; j < 8; j++) { q0[j] = z0 ? 0ull : p0[j]; q1[j] = p1[j]; }
        }
        attn_scan2<true>(q0, q1, Ks + 1*4, Vs + 1*4, NPICK, l0, l1, o0, o1);
        {
            const u64* p0 = (const u64*)(g_QB + qi0);
            const u64* p1 = (const u64*)(g_QB + qi1);
#pragma unroll
            for (int j = 0; j < 8; j++) { q0[j] = z0 ? 0ull : p0[j]; q1[j] = p1[j]; }
        }
        attn_scan2<true>(q0, q1, Ks + (1+NPICK)*4, Vs + (1+NPICK)*4, NDEL, l0, l1, o0, o1);
    }

    // token-major writes: g_heads3[b*Gg + row][h*16 + v]  (4x STG.128)
    {
        const u64 iv0 = dup2(1.f / l0);
        u64* hp = (u64*)(g_heads3 + (size_t)(b*Gg + r0)*128 + h*16);
#pragma unroll
        for (int j = 0; j < 8; j++) hp[j] = mul2(o0[j], iv0);
    }
    if (has1) {
        const u64 iv1 = dup2(1.f / l1);
        u64* hp = (u64*)(g_heads3 + (size_t)(b*Gg + r1)*128 + h*16);
#pragma unroll
        for (int j = 0; j < 8; j++) hp[j] = mul2(o1[j], iv1);
    }
}

// ==========================================================================
// Kernel 3: out[token][e] = sum_hv heads3[token][hv] * W_out[hv][e]
// Pure token-major GEMM.  126 blocks x 256 threads, single wave.
// launch_bounds(256,1): only 1 block fits in smem anyway -> let ptxas use
// up to 255 regs and software-pipeline the LDS->fma2 chains.
// ==========================================================================
#define OT_GT  64
#define W_PAD  130
#define K3_SMEM ((128*W_PAD + OT_GT*128)*4)   // 99328 B

__global__ void __launch_bounds__(256, 1) out_kernel(const float* __restrict__ Wo,
                                                     float* __restrict__ out)
{
    extern __shared__ float sm[];
    float* Bs = sm;                  // 128 x 130 (W_out, padded rows)
    float* As = sm + 128*W_PAD;      // 64 tokens x 128 hv (token-major)

    const int t0  = blockIdx.x * OT_GT;
    const int tid = threadIdx.x;

    {   // stage W_out: 128x128, rows padded to 130
        const float2* src = (const float2*)Wo;
        for (int i = tid; i < 128*64; i += 256) {
            int r = i >> 6, c = i & 63;
            *(float2*)(Bs + r*W_PAD + 2*c) = src[i];
        }
    }
    {   // stage A tile: heads3[t0..t0+63][0..127]  (coalesced float4)
        const float4* src = (const float4*)(g_heads3 + (size_t)t0*128);
        float4* dst = (float4*)As;
#pragma unroll
        for (int i = 0; i < 8; i++) dst[tid + i*256] = src[tid + i*256];
    }
    __syncthreads();

    const int elane = tid & 15;      // 8 e-cols as u64 pairs: col = elane+16j
    const int grow  = tid >> 4;      // 16 grows x 4 tokens each

    u64 acc[4][4];
#pragma unroll
    for (int gg = 0; gg < 4; gg++)
#pragma unroll
        for (int j = 0; j < 4; j++) acc[gg][j] = 0ull;

    const float* Ap = As + grow*4*128;           // 4 token rows of 128
    const u64*   Bp = (const u64*)Bs + elane;    // row stride 65 u64

#pragma unroll 8
    for (int hv = 0; hv < 128; hv++) {
        float a0 = Ap[hv];
        float a1 = Ap[hv + 128];
        float a2 = Ap[hv + 256];
        float a3 = Ap[hv + 384];
        u64 b0 = Bp[hv*65];
        u64 b1 = Bp[hv*65 + 16];
        u64 b2 = Bp[hv*65 + 32];
        u64 b3 = Bp[hv*65 + 48];
        u64 aa0 = dup2(a0), aa1 = dup2(a1), aa2 = dup2(a2), aa3 = dup2(a3);
        acc[0][0] = fma2(b0, aa0, acc[0][0]);
        acc[1][0] = fma2(b0, aa1, acc[1][0]);
        acc[2][0] = fma2(b0, aa2, acc[2][0]);
        acc[3][0] = fma2(b0, aa3, acc[3][0]);
        acc[0][1] = fma2(b1, aa0, acc[0][1]);
        acc[1][1] = fma2(b1, aa1, acc[1][1]);
        acc[2][1] = fma2(b1, aa2, acc[2][1]);
        acc[3][1] = fma2(b1, aa3, acc[3][1]);
        acc[0][2] = fma2(b2, aa0, acc[0][2]);
        acc[1][2] = fma2(b2, aa1, acc[1][2]);
        acc[2][2] = fma2(b2, aa2, acc[2][2]);
        acc[3][2] = fma2(b2, aa3, acc[3][2]);
        acc[0][3] = fma2(b3, aa0, acc[0][3]);
        acc[1][3] = fma2(b3, aa1, acc[1][3]);
        acc[2][3] = fma2(b3, aa2, acc[2][3]);
        acc[3][3] = fma2(b3, aa3, acc[3][3]);
    }

#pragma unroll
    for (int gg = 0; gg < 4; gg++) {
        const int token = t0 + grow*4 + gg;
        if (token < NTOK) {
            float* op = out + (size_t)token*Ee;
#pragma unroll
            for (int j = 0; j < 4; j++) {
                float x, y; upk(acc[gg][j], x, y);
                *(float2*)(op + 2*(elane + 16*j)) = make_float2(x, y);
            }
        }
    }
}

// ==========================================================================
extern "C" void kernel_launch(void* const* d_in, const int* in_sizes, int n_in,
                              void* d_out, int out_size)
{
    const float* q  = (const float*)d_in[0];
    const float* Wq = (const float*)d_in[1];
    const float* Wk = (const float*)d_in[2];
    const float* Wv = (const float*)d_in[3];
    const float* W1 = (const float*)d_in[4];
    const float* W2 = (const float*)d_in[5];
    const float* W3 = (const float*)d_in[6];
    const float* W4 = (const float*)d_in[7];
    const float* Wo = (const float*)d_in[8];
    float* out = (float*)d_out;

    cudaFuncSetAttribute(proj_kernel, cudaFuncAttributeMaxDynamicSharedMemorySize, K1_SMEM);
    cudaFuncSetAttribute(attn_kernel, cudaFuncAttributeMaxDynamicSharedMemorySize, K2_SMEM);
    cudaFuncSetAttribute(out_kernel,  cudaFuncAttributeMaxDynamicSharedMemorySize, K3_SMEM);

    dim3 g0(7, Hh);
    wprep_kernel<<<g0, 256>>>(Wq, Wk, Wv, W1, W2, W3, W4);

    dim3 g1(PB, Hh);                                // (19, 8) persistent
    proj_kernel<<<g1, 256, K1_SMEM>>>(q);

    dim3 g2(Bb, Hh);                                // 128 blocks x 256 threads
    attn_kernel<<<g2, 256, K2_SMEM>>>();

    out_kernel<<<NTOKP/OT_GT, 256, K3_SMEM>>>(Wo, out);   // 126 blocks
}

// round 15
// speedup vs baseline: 1.0113x; 1.0113x over previous
#include <cuda_runtime.h>
#include <cuda_bf16.h>
#include <math.h>

#define Hh   8
#define Dm   128
#define Ee   128
#define KDk  16
#define Bb   16
#define NPICK 250
#define NDEL  250
#define Gg   501            // 1 + NPICK + NDEL
#define NTOK (Bb*Gg)        // 8016
#define NTOKP 8064          // padded token count (64-token tiles)

typedef unsigned long long u64;

// ---------------- packed f32x2 helpers (FFMA2 path, 2x fp32 rate) ----------
__device__ __forceinline__ u64 fma2(u64 a, u64 b, u64 c) {
    u64 d; asm("fma.rn.f32x2 %0, %1, %2, %3;" : "=l"(d) : "l"(a), "l"(b), "l"(c));
    return d;
}
__device__ __forceinline__ u64 mul2(u64 a, u64 b) {
    u64 d; asm("mul.rn.f32x2 %0, %1, %2;" : "=l"(d) : "l"(a), "l"(b));
    return d;
}
__device__ __forceinline__ u64 add2(u64 a, u64 b) {
    u64 d; asm("add.rn.f32x2 %0, %1, %2;" : "=l"(d) : "l"(a), "l"(b));
    return d;
}
__device__ __forceinline__ void upk(u64 a, float& x, float& y) {
    asm("mov.b64 {%0, %1}, %2;" : "=f"(x), "=f"(y) : "l"(a));
}
__device__ __forceinline__ u64 dup2(float x) {
    u64 r; asm("mov.b64 %0, {%1, %1};" : "=l"(r) : "f"(x));
    return r;
}
__device__ __forceinline__ float ex2f(float x) {
    float r; asm("ex2.approx.ftz.f32 %0, %1;" : "=f"(r) : "f"(x));
    return r;
}

union F4 { float4 v; u64 p[2]; };

// ---------------- device scratch ----------------
#define WPAD 132
__device__ float g_Wt[Hh*7*KDk*WPAD];       // transposed+padded weights
__device__ float g_K [Hh*Bb*Gg*KDk];
__device__ float g_V [Hh*Bb*Gg*KDk];
__device__ float g_Qm[Hh*Bb*Gg*KDk];        // pre-scaled by nf*log2(e)
__device__ float g_QA[Hh*Bb*Gg*KDk];
__device__ float g_QB[Hh*Bb*Gg*KDk];
__device__ float g_heads3[NTOKP*128];       // token-major heads [token][h*16+v]

#define SCL   (0.25f * 1.44269504f)    // 1/sqrt(KD) * log2(e)
#define M2OFF 16.0f                    // fixed softmax offset (log2 units)

// ==========================================================================
// Kernel 0: weight prep.  g_Wt[h][m*16+k][d] = W_m[h][d][k]  (row pad 132)
// ==========================================================================
__global__ void wprep_kernel(const float* __restrict__ Wq, const float* __restrict__ Wk,
                             const float* __restrict__ Wv, const float* __restrict__ W1,
                             const float* __restrict__ W2, const float* __restrict__ W3,
                             const float* __restrict__ W4)
{
    const float* Ws[7] = {Wq, Wk, Wv, W1, W2, W3, W4};
    const int m = blockIdx.x, h = blockIdx.y;
    const float* w = Ws[m] + h * (Dm*KDk);
    float* dst = g_Wt + (size_t)(h*7*KDk + m*KDk) * WPAD;
    for (int idx = threadIdx.x; idx < Dm*KDk; idx += 256) {
        int d = idx >> 4, k = idx & 15;
        dst[k*WPAD + d] = w[idx];
    }
}

// ==========================================================================
// Kernel 1: projections (round-13 config).  Block = (80-token chunk, head),
// 256 threads.  thread (k, tg): 5 tokens x 7 mats, fma2 inner loop.
// ==========================================================================
#define PT_TOK 80
#define QPAD   132
#define K1_SMEM ((7*16*WPAD + PT_TOK*QPAD)*4)   // 101376 B

__global__ void __launch_bounds__(256) proj_kernel(const float* __restrict__ q)
{
    extern __shared__ float sm[];
    float* Wt = sm;                         // 112*132
    float* qs = sm + 7*KDk*WPAD;            // 80*132

    const int h    = blockIdx.y;
    const int base = blockIdx.x * PT_TOK;
    const int tid  = threadIdx.x;
    const int nTok = min(PT_TOK, NTOK - base);

    {   // stage padded weights (contiguous float2 copy, L2-hot)
        const float2* src = (const float2*)(g_Wt + (size_t)h*7*KDk*WPAD);
        float2*       dst = (float2*)Wt;
#pragma unroll
        for (int i = 0; i < 29; i++) {      // 29*256 = 7424 >= 7392
            int idx = tid + i*256;
            if (idx < 7*KDk*WPAD/2) dst[idx] = src[idx];
        }
    }
    {   // stage q rows with padding (float4 granularity)
        const float4* qg = (const float4*)(q + (size_t)base * Dm);
        const int n4 = nTok * (Dm/4);
        for (int idx = tid; idx < n4; idx += 256) {
            int t = idx >> 5, i = idx & 31;
            ((float4*)(qs + t*QPAD))[i] = qg[idx];
        }
    }
    __syncthreads();

    const int k  = tid & 15;
    const int tg = tid >> 4;                // 16 groups x 5 tokens
    const int t0 = tg * 5;

    u64 acc[5][7];
#pragma unroll
    for (int i = 0; i < 5; i++)
#pragma unroll
        for (int m = 0; m < 7; m++) acc[i][m] = 0ull;

    const float4* qr[5];
#pragma unroll
    for (int i = 0; i < 5; i++) qr[i] = (const float4*)(qs + (t0 + i)*QPAD);
    const float4* wr[7];
#pragma unroll
    for (int m = 0; m < 7; m++) wr[m] = (const float4*)(Wt + (m*16 + k)*WPAD);

#pragma unroll 2
    for (int d4 = 0; d4 < Dm/4; d4++) {
        F4 qv[5];
#pragma unroll
        for (int i = 0; i < 5; i++) qv[i].v = qr[i][d4];
#pragma unroll
        for (int m = 0; m < 7; m++) {
            F4 w; w.v = wr[m][d4];
#pragma unroll
            for (int i = 0; i < 5; i++) {
                acc[i][m] = fma2(qv[i].p[0], w.p[0], acc[i][m]);
                acc[i][m] = fma2(qv[i].p[1], w.p[1], acc[i][m]);
            }
        }
    }

#pragma unroll
    for (int i = 0; i < 5; i++) {
        if (t0 + i >= nTok) break;
        float s[7];
#pragma unroll
        for (int m = 0; m < 7; m++) { float x, y; upk(acc[i][m], x, y); s[m] = x + y; }
        const int token = base + t0 + i;
        const int b = token / Gg;
        const int g = token - b * Gg;
        const bool pick = (g >= 1 && g <= NPICK);
        const int idx = ((h*Bb + b)*Gg + g)*KDk + k;
        g_Qm[idx] = s[0] * SCL;
        g_K [idx] = s[1];
        g_V [idx] = s[2];
        g_QA[idx] = (pick ? s[3] : s[5]) * SCL;
        g_QB[idx] = (pick ? s[4] : s[6]) * SCL;
    }
}

// ==========================================================================
// Kernel 2: fused attention (round-9 config; token-major output writes).
// Block = (b,h): 128 blocks x 256 threads, TWO q-rows per thread.
// ==========================================================================
#define K2_SMEM (2*Gg*KDk*4)   // 64128 B

template<bool ZMASK>
__device__ __forceinline__ void attn_scan2(const u64* __restrict__ q0,
                                           const u64* __restrict__ q1,
                                           const float4* __restrict__ Kb,
                                           const float4* __restrict__ Vb,
                                           int n,
                                           float& l0, float& l1,
                                           u64* __restrict__ o0,
                                           u64* __restrict__ o1)
{
#pragma unroll 2
    for (int g = 0; g < n; g++) {
        F4 k0, k1, k2, k3;
        k0.v = Kb[g*4+0]; k1.v = Kb[g*4+1];
        k2.v = Kb[g*4+2]; k3.v = Kb[g*4+3];

        u64 a0 = mul2(q0[0], k0.p[0]);
        u64 a1 = mul2(q0[1], k0.p[1]);
        u64 c0 = mul2(q1[0], k0.p[0]);
        u64 c1 = mul2(q1[1], k0.p[1]);
        a0 = fma2(q0[2], k1.p[0], a0);
        a1 = fma2(q0[3], k1.p[1], a1);
        c0 = fma2(q1[2], k1.p[0], c0);
        c1 = fma2(q1[3], k1.p[1], c1);
        a0 = fma2(q0[4], k2.p[0], a0);
        a1 = fma2(q0[5], k2.p[1], a1);
        c0 = fma2(q1[4], k2.p[0], c0);
        c1 = fma2(q1[5], k2.p[1], c1);
        a0 = fma2(q0[6], k3.p[0], a0);
        a1 = fma2(q0[7], k3.p[1], a1);
        c0 = fma2(q1[6], k3.p[0], c0);
        c1 = fma2(q1[7], k3.p[1], c1);
        a0 = add2(a0, a1);
        c0 = add2(c0, c1);

        // V loads issued before the MUFU so LDS latency overlaps exp
        F4 v0, v1, v2, v3;
        v0.v = Vb[g*4+0]; v1.v = Vb[g*4+1];
        v2.v = Vb[g*4+2]; v3.v = Vb[g*4+3];

        float x, y;
        upk(a0, x, y); float s0 = x + y;
        upk(c0, x, y); float s1 = x + y;
        float p0 = ex2f(s0 - M2OFF);
        float p1 = ex2f(s1 - M2OFF);
        if (ZMASK) {                       // zmask: score==0 -> excluded
            p0 = (s0 == 0.f) ? 0.f : p0;
            p1 = (s1 == 0.f) ? 0.f : p1;
        }
        l0 += p0;
        l1 += p1;
        u64 pp0 = dup2(p0), pp1 = dup2(p1);
        o0[0] = fma2(pp0, v0.p[0], o0[0]);
        o1[0] = fma2(pp1, v0.p[0], o1[0]);
        o0[1] = fma2(pp0, v0.p[1], o0[1]);
        o1[1] = fma2(pp1, v0.p[1], o1[1]);
        o0[2] = fma2(pp0, v1.p[0], o0[2]);
        o1[2] = fma2(pp1, v1.p[0], o1[2]);
        o0[3] = fma2(pp0, v1.p[1], o0[3]);
        o1[3] = fma2(pp1, v1.p[1], o1[3]);
        o0[4] = fma2(pp0, v2.p[0], o0[4]);
        o1[4] = fma2(pp1, v2.p[0], o1[4]);
        o0[5] = fma2(pp0, v2.p[1], o0[5]);
        o1[5] = fma2(pp1, v2.p[1], o1[5]);
        o0[6] = fma2(pp0, v3.p[0], o0[6]);
        o1[6] = fma2(pp1, v3.p[0], o1[6]);
        o0[7] = fma2(pp0, v3.p[1], o0[7]);
        o1[7] = fma2(pp1, v3.p[1], o1[7]);
    }
}

__global__ void __launch_bounds__(256) attn_kernel()
{
    extern __shared__ float sm[];

    const int b  = blockIdx.x;
    const int h  = blockIdx.y;
    const int tid = threadIdx.x;
    const int hb  = h*Bb + b;

    {   // stage K,V for this (h,b): 501 x 16 floats each
        const float4* Kg = (const float4*)(g_K + (size_t)hb * Gg * KDk);
        const float4* Vg = (const float4*)(g_V + (size_t)hb * Gg * KDk);
        float4* Ks4 = (float4*)sm;
        float4* Vs4 = (float4*)(sm + Gg*KDk);
        for (int i = tid; i < Gg*4; i += 256) { Ks4[i] = Kg[i]; Vs4[i] = Vg[i]; }
    }
    __syncthreads();

    const float4* Ks = (const float4*)sm;
    const float4* Vs = Ks + Gg*4;

    const int r0 = tid;                         // always < 501
    const bool has1 = (tid + 256 < Gg);
    const int r1 = has1 ? (tid + 256) : (Gg - 1);   // clamped; output guarded

    const int qi0 = (hb*Gg + r0)*KDk;
    const int qi1 = (hb*Gg + r1)*KDk;

    float l0 = 0.f, l1 = 0.f;
    u64 o0[8], o1[8];
#pragma unroll
    for (int j = 0; j < 8; j++) { o0[j] = 0ull; o1[j] = 0ull; }

    {   // ---- main block: 501 keys, no mask ----
        u64 q0[8], q1[8];
        const u64* p0 = (const u64*)(g_Qm + qi0);
        const u64* p1 = (const u64*)(g_Qm + qi1);
#pragma unroll
        for (int j = 0; j < 8; j++) { q0[j] = p0[j]; q1[j] = p1[j]; }
        attn_scan2<false>(q0, q1, Ks, Vs, Gg, l0, l1, o0, o1);
    }

    {   // ---- extra blocks; row 0 gets zeroed Q -> s==0 -> masked out ----
        const bool z0 = (r0 == 0);
        u64 q0[8], q1[8];
        {
            const u64* p0 = (const u64*)(g_QA + qi0);
            const u64* p1 = (const u64*)(g_QA + qi1);
#pragma unroll
            for (int j = 0; j < 8; j++) { q0[j] = z0 ? 0ull : p0[j]; q1[j] = p1[j]; }
        }
        attn_scan2<true>(q0, q1, Ks + 1*4, Vs + 1*4, NPICK, l0, l1, o0, o1);
        {
            const u64* p0 = (const u64*)(g_QB + qi0);
            const u64* p1 = (const u64*)(g_QB + qi1);
#pragma unroll
            for (int j = 0; j < 8; j++) { q0[j] = z0 ? 0ull : p0[j]; q1[j] = p1[j]; }
        }
        attn_scan2<true>(q0, q1, Ks + (1+NPICK)*4, Vs + (1+NPICK)*4, NDEL, l0, l1, o0, o1);
    }

    // token-major writes: g_heads3[b*Gg + row][h*16 + v]  (4x STG.128)
    {
        const u64 iv0 = dup2(1.f / l0);
        u64* hp = (u64*)(g_heads3 + (size_t)(b*Gg + r0)*128 + h*16);
#pragma unroll
        for (int j = 0; j < 8; j++) hp[j] = mul2(o0[j], iv0);
    }
    if (has1) {
        const u64 iv1 = dup2(1.f / l1);
        u64* hp = (u64*)(g_heads3 + (size_t)(b*Gg + r1)*128 + h*16);
#pragma unroll
        for (int j = 0; j < 8; j++) hp[j] = mul2(o1[j], iv1);
    }
}

// ==========================================================================
// Kernel 3: out[token][e] = sum_hv heads3[token][hv] * W_out[hv][e]
// Token-major GEMM with PRE-DUPLICATED A tile: AsD[token][hv] = (a,a) u64.
// Inner loop = pure 8x LDS.64 + 16x FFMA2, zero ALU.
// 126 blocks x 256 threads, single wave.  Thread: 4 tokens x 8 e-cols.
// ==========================================================================
#define OT_GT  64
#define W_PAD  130
#define AROW   130     // u64 per A row (stride ≡ 4 mod 32 banks)
#define K3_SMEM (128*W_PAD*4 + OT_GT*AROW*8)   // 66560 + 66560 = 133120 B

__global__ void __launch_bounds__(256) out_kernel(const float* __restrict__ Wo,
                                                  float* __restrict__ out)
{
    extern __shared__ float sm[];
    float* Bs  = sm;                          // 128 x 130 floats (W_out)
    u64*   AsD = (u64*)(sm + 128*W_PAD);      // 64 tokens x 130 u64 (dup pairs)

    const int t0  = blockIdx.x * OT_GT;
    const int tid = threadIdx.x;

    {   // stage W_out: 128x128, rows padded to 130
        const float2* src = (const float2*)Wo;
        for (int i = tid; i < 128*64; i += 256) {
            int r = i >> 6, c = i & 63;
            *(float2*)(Bs + r*W_PAD + 2*c) = src[i];
        }
    }
    {   // stage A tile pre-duplicated: AsD[tok][hv] = (a,a)
        const float4* src = (const float4*)(g_heads3 + (size_t)t0*128);
#pragma unroll
        for (int i = 0; i < 8; i++) {
            int idx = tid + i*256;             // 2048 float4 total
            int tok = idx >> 5, c = idx & 31;  // c = float4 index in row
            float4 v = src[idx];
            u64* dst = AsD + tok*AROW + c*4;
            dst[0] = dup2(v.x);
            dst[1] = dup2(v.y);
            dst[2] = dup2(v.z);
            dst[3] = dup2(v.w);
        }
    }
    __syncthreads();

    const int elane = tid & 15;      // 8 e-cols as u64 pairs: col = elane+16j
    const int grow  = tid >> 4;      // 16 grows x 4 tokens each

    u64 acc[4][4];
#pragma unroll
    for (int gg = 0; gg < 4; gg++)
#pragma unroll
        for (int j = 0; j < 4; j++) acc[gg][j] = 0ull;

    const u64* Ap = AsD + grow*4*AROW;           // 4 token rows, stride AROW
    const u64* Bp = (const u64*)Bs + elane;      // row stride 65 u64

#pragma unroll 8
    for (int hv = 0; hv < 128; hv++) {
        u64 a0 = Ap[hv];
        u64 a1 = Ap[hv + AROW];
        u64 a2 = Ap[hv + 2*AROW];
        u64 a3 = Ap[hv + 3*AROW];
        u64 b0 = Bp[hv*65];
        u64 b1 = Bp[hv*65 + 16];
        u64 b2 = Bp[hv*65 + 32];
        u64 b3 = Bp[hv*65 + 48];
        acc[0][0] = fma2(b0, a0, acc[0][0]);
        acc[1][0] = fma2(b0, a1, acc[1][0]);
        acc[2][0] = fma2(b0, a2, acc[2][0]);
        acc[3][0] = fma2(b0, a3, acc[3][0]);
        acc[0][1] = fma2(b1, a0, acc[0][1]);
        acc[1][1] = fma2(b1, a1, acc[1][1]);
        acc[2][1] = fma2(b1, a2, acc[2][1]);
        acc[3][1] = fma2(b1, a3, acc[3][1]);
        acc[0][2] = fma2(b2, a0, acc[0][2]);
        acc[1][2] = fma2(b2, a1, acc[1][2]);
        acc[2][2] = fma2(b2, a2, acc[2][2]);
        acc[3][2] = fma2(b2, a3, acc[3][2]);
        acc[0][3] = fma2(b3, a0, acc[0][3]);
        acc[1][3] = fma2(b3, a1, acc[1][3]);
        acc[2][3] = fma2(b3, a2, acc[2][3]);
        acc[3][3] = fma2(b3, a3, acc[3][3]);
    }

#pragma unroll
    for (int gg = 0; gg < 4; gg++) {
        const int token = t0 + grow*4 + gg;
        if (token < NTOK) {
            float* op = out + (size_t)token*Ee;
#pragma unroll
            for (int j = 0; j < 4; j++) {
                float x, y; upk(acc[gg][j], x, y);
                *(float2*)(op + 2*(elane + 16*j)) = make_float2(x, y);
            }
        }
    }
}

// ==========================================================================
extern "C" void kernel_launch(void* const* d_in, const int* in_sizes, int n_in,
                              void* d_out, int out_size)
{
    const float* q  = (const float*)d_in[0];
    const float* Wq = (const float*)d_in[1];
    const float* Wk = (const float*)d_in[2];
    const float* Wv = (const float*)d_in[3];
    const float* W1 = (const float*)d_in[4];
    const float* W2 = (const float*)d_in[5];
    const float* W3 = (const float*)d_in[6];
    const float* W4 = (const float*)d_in[7];
    const float* Wo = (const float*)d_in[8];
    float* out = (float*)d_out;

    cudaFuncSetAttribute(proj_kernel, cudaFuncAttributeMaxDynamicSharedMemorySize, K1_SMEM);
    cudaFuncSetAttribute(attn_kernel, cudaFuncAttributeMaxDynamicSharedMemorySize, K2_SMEM);
    cudaFuncSetAttribute(out_kernel,  cudaFuncAttributeMaxDynamicSharedMemorySize, K3_SMEM);

    dim3 g0(7, Hh);
    wprep_kernel<<<g0, 256>>>(Wq, Wk, Wv, W1, W2, W3, W4);

    dim3 g1((NTOK + PT_TOK - 1)/PT_TOK, Hh);        // (101, 8)
    proj_kernel<<<g1, 256, K1_SMEM>>>(q);

    dim3 g2(Bb, Hh);                                // 128 blocks x 256 threads
    attn_kernel<<<g2, 256, K2_SMEM>>>();

    out_kernel<<<NTOKP/OT_GT, 256, K3_SMEM>>>(Wo, out);   // 126 blocks
}

// round 16
// speedup vs baseline: 1.0366x; 1.0250x over previous
#include <cuda_runtime.h>
#include <cuda_bf16.h>
#include <math.h>

#define Hh   8
#define Dm   128
#define Ee   128
#define KDk  16
#define Bb   16
#define NPICK 250
#define NDEL  250
#define Gg   501            // 1 + NPICK + NDEL
#define NTOK (Bb*Gg)        // 8016
#define NTOKP 8064          // padded token count (64-token tiles)

typedef unsigned long long u64;

// ---------------- packed f32x2 helpers (FFMA2 path, 2x fp32 rate) ----------
__device__ __forceinline__ u64 fma2(u64 a, u64 b, u64 c) {
    u64 d; asm("fma.rn.f32x2 %0, %1, %2, %3;" : "=l"(d) : "l"(a), "l"(b), "l"(c));
    return d;
}
__device__ __forceinline__ u64 mul2(u64 a, u64 b) {
    u64 d; asm("mul.rn.f32x2 %0, %1, %2;" : "=l"(d) : "l"(a), "l"(b));
    return d;
}
__device__ __forceinline__ u64 add2(u64 a, u64 b) {
    u64 d; asm("add.rn.f32x2 %0, %1, %2;" : "=l"(d) : "l"(a), "l"(b));
    return d;
}
__device__ __forceinline__ void upk(u64 a, float& x, float& y) {
    asm("mov.b64 {%0, %1}, %2;" : "=f"(x), "=f"(y) : "l"(a));
}
__device__ __forceinline__ u64 dup2(float x) {
    u64 r; asm("mov.b64 %0, {%1, %1};" : "=l"(r) : "f"(x));
    return r;
}
__device__ __forceinline__ float ex2f(float x) {
    float r; asm("ex2.approx.ftz.f32 %0, %1;" : "=f"(r) : "f"(x));
    return r;
}

union F4 { float4 v; u64 p[2]; };

// ---------------- device scratch ----------------
#define WPAD 132
__device__ float g_Wt[Hh*7*KDk*WPAD];       // transposed+padded weights
__device__ float g_K [Hh*Bb*Gg*KDk];
__device__ float g_V [Hh*Bb*Gg*KDk];
__device__ float g_Qm[Hh*Bb*Gg*KDk];        // pre-scaled by nf*log2(e)
__device__ float g_QA[Hh*Bb*Gg*KDk];
__device__ float g_QB[Hh*Bb*Gg*KDk];
__device__ float g_heads3[NTOKP*128];       // token-major heads [token][h*16+v]

#define SCL   (0.25f * 1.44269504f)    // 1/sqrt(KD) * log2(e)
#define M2OFF 16.0f                    // fixed softmax offset (log2 units)

// ==========================================================================
// Kernel 0: weight prep.  g_Wt[h][m*16+k][d] = W_m[h][d][k]  (row pad 132)
// ==========================================================================
__global__ void wprep_kernel(const float* __restrict__ Wq, const float* __restrict__ Wk,
                             const float* __restrict__ Wv, const float* __restrict__ W1,
                             const float* __restrict__ W2, const float* __restrict__ W3,
                             const float* __restrict__ W4)
{
    const float* Ws[7] = {Wq, Wk, Wv, W1, W2, W3, W4};
    const int m = blockIdx.x, h = blockIdx.y;
    const float* w = Ws[m] + h * (Dm*KDk);
    float* dst = g_Wt + (size_t)(h*7*KDk + m*KDk) * WPAD;
    for (int idx = threadIdx.x; idx < Dm*KDk; idx += 256) {
        int d = idx >> 4, k = idx & 15;
        dst[k*WPAD + d] = w[idx];
    }
}

// ==========================================================================
// Kernel 1: projections.  Block = (64-token chunk, head), 256 threads,
// 2 blocks/SM co-resident (92.9KB smem, 128-reg cap — fits 4-token tile).
// thread (k = tid&15, tg = tid>>4): 4 tokens x 7 mats, fma2 inner loop.
// ==========================================================================
#define PT_TOK 64
#define QPAD   132
#define K1_SMEM ((7*16*WPAD + PT_TOK*QPAD)*4)   // 92928 B

__global__ void __launch_bounds__(256, 2) proj_kernel(const float* __restrict__ q)
{
    extern __shared__ float sm[];
    float* Wt = sm;                         // 112*132
    float* qs = sm + 7*KDk*WPAD;            // 64*132

    const int h    = blockIdx.y;
    const int base = blockIdx.x * PT_TOK;
    const int tid  = threadIdx.x;
    const int nTok = min(PT_TOK, NTOK - base);

    {   // stage padded weights (contiguous float2 copy, L2-hot)
        const float2* src = (const float2*)(g_Wt + (size_t)h*7*KDk*WPAD);
        float2*       dst = (float2*)Wt;
#pragma unroll
        for (int i = 0; i < 29; i++) {      // 29*256 = 7424 >= 7392
            int idx = tid + i*256;
            if (idx < 7*KDk*WPAD/2) dst[idx] = src[idx];
        }
    }
    {   // stage q rows with padding (float4 granularity)
        const float4* qg = (const float4*)(q + (size_t)base * Dm);
        const int n4 = nTok * (Dm/4);
        for (int idx = tid; idx < n4; idx += 256) {
            int t = idx >> 5, i = idx & 31;
            ((float4*)(qs + t*QPAD))[i] = qg[idx];
        }
    }
    __syncthreads();

    const int k  = tid & 15;
    const int tg = tid >> 4;                // 16 groups x 4 tokens
    const int t0 = tg * 4;

    u64 acc[4][7];
#pragma unroll
    for (int i = 0; i < 4; i++)
#pragma unroll
        for (int m = 0; m < 7; m++) acc[i][m] = 0ull;

    const float4* qr[4];
#pragma unroll
    for (int i = 0; i < 4; i++) qr[i] = (const float4*)(qs + (t0 + i)*QPAD);
    const float4* wr[7];
#pragma unroll
    for (int m = 0; m < 7; m++) wr[m] = (const float4*)(Wt + (m*16 + k)*WPAD);

#pragma unroll 2
    for (int d4 = 0; d4 < Dm/4; d4++) {
        F4 qv[4];
#pragma unroll
        for (int i = 0; i < 4; i++) qv[i].v = qr[i][d4];
#pragma unroll
        for (int m = 0; m < 7; m++) {
            F4 w; w.v = wr[m][d4];
#pragma unroll
            for (int i = 0; i < 4; i++) {
                acc[i][m] = fma2(qv[i].p[0], w.p[0], acc[i][m]);
                acc[i][m] = fma2(qv[i].p[1], w.p[1], acc[i][m]);
            }
        }
    }

#pragma unroll
    for (int i = 0; i < 4; i++) {
        if (t0 + i >= nTok) break;
        float s[7];
#pragma unroll
        for (int m = 0; m < 7; m++) { float x, y; upk(acc[i][m], x, y); s[m] = x + y; }
        const int token = base + t0 + i;
        const int b = token / Gg;
        const int g = token - b * Gg;
        const bool pick = (g >= 1 && g <= NPICK);
        const int idx = ((h*Bb + b)*Gg + g)*KDk + k;
        g_Qm[idx] = s[0] * SCL;
        g_K [idx] = s[1];
        g_V [idx] = s[2];
        g_QA[idx] = (pick ? s[3] : s[5]) * SCL;
        g_QB[idx] = (pick ? s[4] : s[6]) * SCL;
    }
}

// ==========================================================================
// Kernel 2: fused attention (round-9 config; token-major output writes).
// Block = (b,h): 128 blocks x 256 threads, TWO q-rows per thread.
// ==========================================================================
#define K2_SMEM (2*Gg*KDk*4)   // 64128 B

template<bool ZMASK>
__device__ __forceinline__ void attn_scan2(const u64* __restrict__ q0,
                                           const u64* __restrict__ q1,
                                           const float4* __restrict__ Kb,
                                           const float4* __restrict__ Vb,
                                           int n,
                                           float& l0, float& l1,
                                           u64* __restrict__ o0,
                                           u64* __restrict__ o1)
{
#pragma unroll 2
    for (int g = 0; g < n; g++) {
        F4 k0, k1, k2, k3;
        k0.v = Kb[g*4+0]; k1.v = Kb[g*4+1];
        k2.v = Kb[g*4+2]; k3.v = Kb[g*4+3];

        u64 a0 = mul2(q0[0], k0.p[0]);
        u64 a1 = mul2(q0[1], k0.p[1]);
        u64 c0 = mul2(q1[0], k0.p[0]);
        u64 c1 = mul2(q1[1], k0.p[1]);
        a0 = fma2(q0[2], k1.p[0], a0);
        a1 = fma2(q0[3], k1.p[1], a1);
        c0 = fma2(q1[2], k1.p[0], c0);
        c1 = fma2(q1[3], k1.p[1], c1);
        a0 = fma2(q0[4], k2.p[0], a0);
        a1 = fma2(q0[5], k2.p[1], a1);
        c0 = fma2(q1[4], k2.p[0], c0);
        c1 = fma2(q1[5], k2.p[1], c1);
        a0 = fma2(q0[6], k3.p[0], a0);
        a1 = fma2(q0[7], k3.p[1], a1);
        c0 = fma2(q1[6], k3.p[0], c0);
        c1 = fma2(q1[7], k3.p[1], c1);
        a0 = add2(a0, a1);
        c0 = add2(c0, c1);

        // V loads issued before the MUFU so LDS latency overlaps exp
        F4 v0, v1, v2, v3;
        v0.v = Vb[g*4+0]; v1.v = Vb[g*4+1];
        v2.v = Vb[g*4+2]; v3.v = Vb[g*4+3];

        float x, y;
        upk(a0, x, y); float s0 = x + y;
        upk(c0, x, y); float s1 = x + y;
        float p0 = ex2f(s0 - M2OFF);
        float p1 = ex2f(s1 - M2OFF);
        if (ZMASK) {                       // zmask: score==0 -> excluded
            p0 = (s0 == 0.f) ? 0.f : p0;
            p1 = (s1 == 0.f) ? 0.f : p1;
        }
        l0 += p0;
        l1 += p1;
        u64 pp0 = dup2(p0), pp1 = dup2(p1);
        o0[0] = fma2(pp0, v0.p[0], o0[0]);
        o1[0] = fma2(pp1, v0.p[0], o1[0]);
        o0[1] = fma2(pp0, v0.p[1], o0[1]);
        o1[1] = fma2(pp1, v0.p[1], o1[1]);
        o0[2] = fma2(pp0, v1.p[0], o0[2]);
        o1[2] = fma2(pp1, v1.p[0], o1[2]);
        o0[3] = fma2(pp0, v1.p[1], o0[3]);
        o1[3] = fma2(pp1, v1.p[1], o1[3]);
        o0[4] = fma2(pp0, v2.p[0], o0[4]);
        o1[4] = fma2(pp1, v2.p[0], o1[4]);
        o0[5] = fma2(pp0, v2.p[1], o0[5]);
        o1[5] = fma2(pp1, v2.p[1], o1[5]);
        o0[6] = fma2(pp0, v3.p[0], o0[6]);
        o1[6] = fma2(pp1, v3.p[0], o1[6]);
        o0[7] = fma2(pp0, v3.p[1], o0[7]);
        o1[7] = fma2(pp1, v3.p[1], o1[7]);
    }
}

__global__ void __launch_bounds__(256) attn_kernel()
{
    extern __shared__ float sm[];

    const int b  = blockIdx.x;
    const int h  = blockIdx.y;
    const int tid = threadIdx.x;
    const int hb  = h*Bb + b;

    {   // stage K,V for this (h,b): 501 x 16 floats each
        const float4* Kg = (const float4*)(g_K + (size_t)hb * Gg * KDk);
        const float4* Vg = (const float4*)(g_V + (size_t)hb * Gg * KDk);
        float4* Ks4 = (float4*)sm;
        float4* Vs4 = (float4*)(sm + Gg*KDk);
        for (int i = tid; i < Gg*4; i += 256) { Ks4[i] = Kg[i]; Vs4[i] = Vg[i]; }
    }
    __syncthreads();

    const float4* Ks = (const float4*)sm;
    const float4* Vs = Ks + Gg*4;

    const int r0 = tid;                         // always < 501
    const bool has1 = (tid + 256 < Gg);
    const int r1 = has1 ? (tid + 256) : (Gg - 1);   // clamped; output guarded

    const int qi0 = (hb*Gg + r0)*KDk;
    const int qi1 = (hb*Gg + r1)*KDk;

    float l0 = 0.f, l1 = 0.f;
    u64 o0[8], o1[8];
#pragma unroll
    for (int j = 0; j < 8; j++) { o0[j] = 0ull; o1[j] = 0ull; }

    {   // ---- main block: 501 keys, no mask ----
        u64 q0[8], q1[8];
        const u64* p0 = (const u64*)(g_Qm + qi0);
        const u64* p1 = (const u64*)(g_Qm + qi1);
#pragma unroll
        for (int j = 0; j < 8; j++) { q0[j] = p0[j]; q1[j] = p1[j]; }
        attn_scan2<false>(q0, q1, Ks, Vs, Gg, l0, l1, o0, o1);
    }

    {   // ---- extra blocks; row 0 gets zeroed Q -> s==0 -> masked out ----
        const bool z0 = (r0 == 0);
        u64 q0[8], q1[8];
        {
            const u64* p0 = (const u64*)(g_QA + qi0);
            const u64* p1 = (const u64*)(g_QA + qi1);
#pragma unroll
            for (int j = 0; j < 8; j++) { q0[j] = z0 ? 0ull : p0[j]; q1[j] = p1[j]; }
        }
        attn_scan2<true>(q0, q1, Ks + 1*4, Vs + 1*4, NPICK, l0, l1, o0, o1);
        {
            const u64* p0 = (const u64*)(g_QB + qi0);
            const u64* p1 = (const u64*)(g_QB + qi1);
#pragma unroll
            for (int j = 0; j < 8; j++) { q0[j] = z0 ? 0ull : p0[j]; q1[j] = p1[j]; }
        }
        attn_scan2<true>(q0, q1, Ks + (1+NPICK)*4, Vs + (1+NPICK)*4, NDEL, l0, l1, o0, o1);
    }

    // token-major writes: g_heads3[b*Gg + row][h*16 + v]  (4x STG.128)
    {
        const u64 iv0 = dup2(1.f / l0);
        u64* hp = (u64*)(g_heads3 + (size_t)(b*Gg + r0)*128 + h*16);
#pragma unroll
        for (int j = 0; j < 8; j++) hp[j] = mul2(o0[j], iv0);
    }
    if (has1) {
        const u64 iv1 = dup2(1.f / l1);
        u64* hp = (u64*)(g_heads3 + (size_t)(b*Gg + r1)*128 + h*16);
#pragma unroll
        for (int j = 0; j < 8; j++) hp[j] = mul2(o1[j], iv1);
    }
}

// ==========================================================================
// Kernel 3: out[token][e] = sum_hv heads3[token][hv] * W_out[hv][e]
// Round-13 config (best measured: 15.4us).  126 blocks x 256 threads.
// Thread (elane, grow): 4g x 8e = 16 acc chains.
// ==========================================================================
#define OT_GT  64
#define W_PAD  130
#define K3_SMEM ((128*W_PAD + OT_GT*128)*4)   // 99328 B

__global__ void __launch_bounds__(256) out_kernel(const float* __restrict__ Wo,
                                                  float* __restrict__ out)
{
    extern __shared__ float sm[];
    float* Bs = sm;                  // 128 x 130 (W_out, padded rows)
    float* As = sm + 128*W_PAD;      // 64 tokens x 128 hv (token-major)

    const int t0  = blockIdx.x * OT_GT;
    const int tid = threadIdx.x;

    {   // stage W_out: 128x128, rows padded to 130
        const float2* src = (const float2*)Wo;
        for (int i = tid; i < 128*64; i += 256) {
            int r = i >> 6, c = i & 63;
            *(float2*)(Bs + r*W_PAD + 2*c) = src[i];
        }
    }
    {   // stage A tile: heads3[t0..t0+63][0..127]  (coalesced float4)
        const float4* src = (const float4*)(g_heads3 + (size_t)t0*128);
        float4* dst = (float4*)As;
#pragma unroll
        for (int i = 0; i < 8; i++) dst[tid + i*256] = src[tid + i*256];
    }
    __syncthreads();

    const int elane = tid & 15;      // 8 e-cols as u64 pairs: col = elane+16j
    const int grow  = tid >> 4;      // 16 grows x 4 tokens each

    u64 acc[4][4];
#pragma unroll
    for (int gg = 0; gg < 4; gg++)
#pragma unroll
        for (int j = 0; j < 4; j++) acc[gg][j] = 0ull;

    const float* Ap = As + grow*4*128;           // 4 token rows of 128
    const u64*   Bp = (const u64*)Bs + elane;    // row stride 65 u64

#pragma unroll 4
    for (int hv = 0; hv < 128; hv++) {
        float a0 = Ap[hv];
        float a1 = Ap[hv + 128];
        float a2 = Ap[hv + 256];
        float a3 = Ap[hv + 384];
        u64 b0 = Bp[hv*65];
        u64 b1 = Bp[hv*65 + 16];
        u64 b2 = Bp[hv*65 + 32];
        u64 b3 = Bp[hv*65 + 48];
        u64 aa0 = dup2(a0), aa1 = dup2(a1), aa2 = dup2(a2), aa3 = dup2(a3);
        acc[0][0] = fma2(b0, aa0, acc[0][0]);
        acc[1][0] = fma2(b0, aa1, acc[1][0]);
        acc[2][0] = fma2(b0, aa2, acc[2][0]);
        acc[3][0] = fma2(b0, aa3, acc[3][0]);
        acc[0][1] = fma2(b1, aa0, acc[0][1]);
        acc[1][1] = fma2(b1, aa1, acc[1][1]);
        acc[2][1] = fma2(b1, aa2, acc[2][1]);
        acc[3][1] = fma2(b1, aa3, acc[3][1]);
        acc[0][2] = fma2(b2, aa0, acc[0][2]);
        acc[1][2] = fma2(b2, aa1, acc[1][2]);
        acc[2][2] = fma2(b2, aa2, acc[2][2]);
        acc[3][2] = fma2(b2, aa3, acc[3][2]);
        acc[0][3] = fma2(b3, aa0, acc[0][3]);
        acc[1][3] = fma2(b3, aa1, acc[1][3]);
        acc[2][3] = fma2(b3, aa2, acc[2][3]);
        acc[3][3] = fma2(b3, aa3, acc[3][3]);
    }

#pragma unroll
    for (int gg = 0; gg < 4; gg++) {
        const int token = t0 + grow*4 + gg;
        if (token < NTOK) {
            float* op = out + (size_t)token*Ee;
#pragma unroll
            for (int j = 0; j < 4; j++) {
                float x, y; upk(acc[gg][j], x, y);
                *(float2*)(op + 2*(elane + 16*j)) = make_float2(x, y);
            }
        }
    }
}

// ==========================================================================
extern "C" void kernel_launch(void* const* d_in, const int* in_sizes, int n_in,
                              void* d_out, int out_size)
{
    const float* q  = (const float*)d_in[0];
    const float* Wq = (const float*)d_in[1];
    const float* Wk = (const float*)d_in[2];
    const float* Wv = (const float*)d_in[3];
    const float* W1 = (const float*)d_in[4];
    const float* W2 = (const float*)d_in[5];
    const float* W3 = (const float*)d_in[6];
    const float* W4 = (const float*)d_in[7];
    const float* Wo = (const float*)d_in[8];
    float* out = (float*)d_out;

    cudaFuncSetAttribute(proj_kernel, cudaFuncAttributeMaxDynamicSharedMemorySize, K1_SMEM);
    cudaFuncSetAttribute(attn_kernel, cudaFuncAttributeMaxDynamicSharedMemorySize, K2_SMEM);
    cudaFuncSetAttribute(out_kernel,  cudaFuncAttributeMaxDynamicSharedMemorySize, K3_SMEM);

    dim3 g0(7, Hh);
    wprep_kernel<<<g0, 256>>>(Wq, Wk, Wv, W1, W2, W3, W4);

    dim3 g1((NTOK + PT_TOK - 1)/PT_TOK, Hh);        // (126, 8)
    proj_kernel<<<g1, 256, K1_SMEM>>>(q);

    dim3 g2(Bb, Hh);                                // 128 blocks x 256 threads
    attn_kernel<<<g2, 256, K2_SMEM>>>();

    out_kernel<<<NTOKP/OT_GT, 256, K3_SMEM>>>(Wo, out);   // 126 blocks
}

// round 17
// speedup vs baseline: 1.2539x; 1.2096x over previous
#include <cuda_runtime.h>
#include <cuda_bf16.h>
#include <math.h>

#define Hh   8
#define Dm   128
#define Ee   128
#define KDk  16
#define Bb   16
#define NPICK 250
#define NDEL  250
#define Gg   501            // 1 + NPICK + NDEL
#define NTOK (Bb*Gg)        // 8016
#define NTOKP 8064          // padded token count (64-token tiles)

typedef unsigned long long u64;

// ---------------- packed f32x2 helpers (FFMA2 path, 2x fp32 rate) ----------
__device__ __forceinline__ u64 fma2(u64 a, u64 b, u64 c) {
    u64 d; asm("fma.rn.f32x2 %0, %1, %2, %3;" : "=l"(d) : "l"(a), "l"(b), "l"(c));
    return d;
}
__device__ __forceinline__ u64 mul2(u64 a, u64 b) {
    u64 d; asm("mul.rn.f32x2 %0, %1, %2;" : "=l"(d) : "l"(a), "l"(b));
    return d;
}
__device__ __forceinline__ u64 add2(u64 a, u64 b) {
    u64 d; asm("add.rn.f32x2 %0, %1, %2;" : "=l"(d) : "l"(a), "l"(b));
    return d;
}
__device__ __forceinline__ void upk(u64 a, float& x, float& y) {
    asm("mov.b64 {%0, %1}, %2;" : "=f"(x), "=f"(y) : "l"(a));
}
__device__ __forceinline__ u64 dup2(float x) {
    u64 r; asm("mov.b64 %0, {%1, %1};" : "=l"(r) : "f"(x));
    return r;
}
__device__ __forceinline__ float ex2f(float x) {
    float r; asm("ex2.approx.ftz.f32 %0, %1;" : "=f"(r) : "f"(x));
    return r;
}

union F4 { float4 v; u64 p[2]; };

// ---------------- device scratch ----------------
#define WPAD 132
__device__ float g_Wt[Hh*7*KDk*WPAD];       // transposed+padded weights
__device__ float g_K [Hh*Bb*Gg*KDk];
__device__ float g_V [Hh*Bb*Gg*KDk];
__device__ float g_Qm[Hh*Bb*Gg*KDk];        // pre-scaled by nf*log2(e)
__device__ float g_QA[Hh*Bb*Gg*KDk];
__device__ float g_QB[Hh*Bb*Gg*KDk];
__device__ float g_heads3[NTOKP*128];       // token-major heads [token][h*16+v]

#define SCL   (0.25f * 1.44269504f)    // 1/sqrt(KD) * log2(e)
#define M2OFF 16.0f                    // fixed softmax offset (log2 units)

// ==========================================================================
// Kernel 0: weight prep.  g_Wt[h][m*16+k][d] = W_m[h][d][k]  (row pad 132)
// ==========================================================================
__global__ void wprep_kernel(const float* __restrict__ Wq, const float* __restrict__ Wk,
                             const float* __restrict__ Wv, const float* __restrict__ W1,
                             const float* __restrict__ W2, const float* __restrict__ W3,
                             const float* __restrict__ W4)
{
    const float* Ws[7] = {Wq, Wk, Wv, W1, W2, W3, W4};
    const int m = blockIdx.x, h = blockIdx.y;
    const float* w = Ws[m] + h * (Dm*KDk);
    float* dst = g_Wt + (size_t)(h*7*KDk + m*KDk) * WPAD;
    for (int idx = threadIdx.x; idx < Dm*KDk; idx += 256) {
        int d = idx >> 4, k = idx & 15;
        dst[k*WPAD + d] = w[idx];
    }
}

// ==========================================================================
// Kernel 1: projections (round-16 config).  Block = (64-token chunk, head),
// 256 threads, 2 blocks/SM.  thread (k, tg): 4 tokens x 7 mats, fma2 loop.
// ==========================================================================
#define PT_TOK 64
#define QPAD   132
#define K1_SMEM ((7*16*WPAD + PT_TOK*QPAD)*4)   // 92928 B

__global__ void __launch_bounds__(256, 2) proj_kernel(const float* __restrict__ q)
{
    extern __shared__ float sm[];
    float* Wt = sm;                         // 112*132
    float* qs = sm + 7*KDk*WPAD;            // 64*132

    const int h    = blockIdx.y;
    const int base = blockIdx.x * PT_TOK;
    const int tid  = threadIdx.x;
    const int nTok = min(PT_TOK, NTOK - base);

    {   // stage padded weights (contiguous float2 copy, L2-hot)
        const float2* src = (const float2*)(g_Wt + (size_t)h*7*KDk*WPAD);
        float2*       dst = (float2*)Wt;
#pragma unroll
        for (int i = 0; i < 29; i++) {      // 29*256 = 7424 >= 7392
            int idx = tid + i*256;
            if (idx < 7*KDk*WPAD/2) dst[idx] = src[idx];
        }
    }
    {   // stage q rows with padding (float4 granularity)
        const float4* qg = (const float4*)(q + (size_t)base * Dm);
        const int n4 = nTok * (Dm/4);
        for (int idx = tid; idx < n4; idx += 256) {
            int t = idx >> 5, i = idx & 31;
            ((float4*)(qs + t*QPAD))[i] = qg[idx];
        }
    }
    __syncthreads();

    const int k  = tid & 15;
    const int tg = tid >> 4;                // 16 groups x 4 tokens
    const int t0 = tg * 4;

    u64 acc[4][7];
#pragma unroll
    for (int i = 0; i < 4; i++)
#pragma unroll
        for (int m = 0; m < 7; m++) acc[i][m] = 0ull;

    const float4* qr[4];
#pragma unroll
    for (int i = 0; i < 4; i++) qr[i] = (const float4*)(qs + (t0 + i)*QPAD);
    const float4* wr[7];
#pragma unroll
    for (int m = 0; m < 7; m++) wr[m] = (const float4*)(Wt + (m*16 + k)*WPAD);

#pragma unroll 2
    for (int d4 = 0; d4 < Dm/4; d4++) {
        F4 qv[4];
#pragma unroll
        for (int i = 0; i < 4; i++) qv[i].v = qr[i][d4];
#pragma unroll
        for (int m = 0; m < 7; m++) {
            F4 w; w.v = wr[m][d4];
#pragma unroll
            for (int i = 0; i < 4; i++) {
                acc[i][m] = fma2(qv[i].p[0], w.p[0], acc[i][m]);
                acc[i][m] = fma2(qv[i].p[1], w.p[1], acc[i][m]);
            }
        }
    }

#pragma unroll
    for (int i = 0; i < 4; i++) {
        if (t0 + i >= nTok) break;
        float s[7];
#pragma unroll
        for (int m = 0; m < 7; m++) { float x, y; upk(acc[i][m], x, y); s[m] = x + y; }
        const int token = base + t0 + i;
        const int b = token / Gg;
        const int g = token - b * Gg;
        const bool pick = (g >= 1 && g <= NPICK);
        const int idx = ((h*Bb + b)*Gg + g)*KDk + k;
        g_Qm[idx] = s[0] * SCL;
        g_K [idx] = s[1];
        g_V [idx] = s[2];
        g_QA[idx] = (pick ? s[3] : s[5]) * SCL;
        g_QB[idx] = (pick ? s[4] : s[6]) * SCL;
    }
}

// ==========================================================================
// Kernel 2: fused attention with MERGED extra-block scan.
// For keys 1..500, the main and extra attention weights multiply the SAME
// V row, so compute both scores per key and do ONE AV accumulate with
// p = p_main + p_extra.  Cuts AV fma2 in half over those keys (-24% work).
// Block = (b,h): 128 blocks x 256 threads, TWO q-rows per thread.
// ==========================================================================
#define K2_SMEM (2*Gg*KDk*4)   // 64128 B

__device__ __forceinline__ float dot8(const u64* __restrict__ q, const u64* kp)
{
    u64 a0 = mul2(q[0], kp[0]);
    u64 a1 = mul2(q[1], kp[1]);
    a0 = fma2(q[2], kp[2], a0);
    a1 = fma2(q[3], kp[3], a1);
    a0 = fma2(q[4], kp[4], a0);
    a1 = fma2(q[5], kp[5], a1);
    a0 = fma2(q[6], kp[6], a0);
    a1 = fma2(q[7], kp[7], a1);
    a0 = add2(a0, a1);
    float x, y; upk(a0, x, y);
    return x + y;
}

// merged scan: two q-rows, two query sets each (main + extra), one AV.
__device__ __forceinline__ void attn_scan_merged(
    const u64* __restrict__ qm0, const u64* __restrict__ qm1,
    const u64* __restrict__ qe0, const u64* __restrict__ qe1,
    const float4* __restrict__ Kb, const float4* __restrict__ Vb, int n,
    float& l0, float& l1, u64* __restrict__ o0, u64* __restrict__ o1)
{
#pragma unroll 2
    for (int g = 0; g < n; g++) {
        F4 kr[4];
        kr[0].v = Kb[g*4+0]; kr[1].v = Kb[g*4+1];
        kr[2].v = Kb[g*4+2]; kr[3].v = Kb[g*4+3];
        const u64* kp = kr[0].p;

        float sm0 = dot8(qm0, kp);
        float sm1 = dot8(qm1, kp);
        float se0 = dot8(qe0, kp);
        float se1 = dot8(qe1, kp);

        // V loads issued before the MUFUs so LDS latency overlaps exp
        F4 v0, v1, v2, v3;
        v0.v = Vb[g*4+0]; v1.v = Vb[g*4+1];
        v2.v = Vb[g*4+2]; v3.v = Vb[g*4+3];

        float pe0 = ex2f(se0 - M2OFF);
        float pe1 = ex2f(se1 - M2OFF);
        pe0 = (se0 == 0.f) ? 0.f : pe0;        // zmask: score==0 -> excluded
        pe1 = (se1 == 0.f) ? 0.f : pe1;
        float p0 = ex2f(sm0 - M2OFF) + pe0;
        float p1 = ex2f(sm1 - M2OFF) + pe1;
        l0 += p0;
        l1 += p1;
        u64 pp0 = dup2(p0), pp1 = dup2(p1);
        o0[0] = fma2(pp0, v0.p[0], o0[0]);
        o1[0] = fma2(pp1, v0.p[0], o1[0]);
        o0[1] = fma2(pp0, v0.p[1], o0[1]);
        o1[1] = fma2(pp1, v0.p[1], o1[1]);
        o0[2] = fma2(pp0, v1.p[0], o0[2]);
        o1[2] = fma2(pp1, v1.p[0], o1[2]);
        o0[3] = fma2(pp0, v1.p[1], o0[3]);
        o1[3] = fma2(pp1, v1.p[1], o1[3]);
        o0[4] = fma2(pp0, v2.p[0], o0[4]);
        o1[4] = fma2(pp1, v2.p[0], o1[4]);
        o0[5] = fma2(pp0, v2.p[1], o0[5]);
        o1[5] = fma2(pp1, v2.p[1], o1[5]);
        o0[6] = fma2(pp0, v3.p[0], o0[6]);
        o1[6] = fma2(pp1, v3.p[0], o1[6]);
        o0[7] = fma2(pp0, v3.p[1], o0[7]);
        o1[7] = fma2(pp1, v3.p[1], o1[7]);
    }
}

__global__ void __launch_bounds__(256) attn_kernel()
{
    extern __shared__ float sm[];

    const int b  = blockIdx.x;
    const int h  = blockIdx.y;
    const int tid = threadIdx.x;
    const int hb  = h*Bb + b;

    {   // stage K,V for this (h,b): 501 x 16 floats each
        const float4* Kg = (const float4*)(g_K + (size_t)hb * Gg * KDk);
        const float4* Vg = (const float4*)(g_V + (size_t)hb * Gg * KDk);
        float4* Ks4 = (float4*)sm;
        float4* Vs4 = (float4*)(sm + Gg*KDk);
        for (int i = tid; i < Gg*4; i += 256) { Ks4[i] = Kg[i]; Vs4[i] = Vg[i]; }
    }
    __syncthreads();

    const float4* Ks = (const float4*)sm;
    const float4* Vs = Ks + Gg*4;

    const int r0 = tid;                         // always < 501
    const bool has1 = (tid + 256 < Gg);
    const int r1 = has1 ? (tid + 256) : (Gg - 1);   // clamped; output guarded

    const int qi0 = (hb*Gg + r0)*KDk;
    const int qi1 = (hb*Gg + r1)*KDk;
    const bool z0 = (r0 == 0);

    float l0 = 0.f, l1 = 0.f;
    u64 o0[8], o1[8];
#pragma unroll
    for (int j = 0; j < 8; j++) { o0[j] = 0ull; o1[j] = 0ull; }

    u64 qm0[8], qm1[8];
    {
        const u64* p0 = (const u64*)(g_Qm + qi0);
        const u64* p1 = (const u64*)(g_Qm + qi1);
#pragma unroll
        for (int j = 0; j < 8; j++) { qm0[j] = p0[j]; qm1[j] = p1[j]; }
    }

    {   // ---- key 0: main only ----
        F4 kr[4];
        kr[0].v = Ks[0]; kr[1].v = Ks[1]; kr[2].v = Ks[2]; kr[3].v = Ks[3];
        float s0 = dot8(qm0, kr[0].p);
        float s1 = dot8(qm1, kr[0].p);
        F4 v0, v1, v2, v3;
        v0.v = Vs[0]; v1.v = Vs[1]; v2.v = Vs[2]; v3.v = Vs[3];
        float p0 = ex2f(s0 - M2OFF);
        float p1 = ex2f(s1 - M2OFF);
        l0 += p0; l1 += p1;
        u64 pp0 = dup2(p0), pp1 = dup2(p1);
        o0[0] = fma2(pp0, v0.p[0], o0[0]);  o1[0] = fma2(pp1, v0.p[0], o1[0]);
        o0[1] = fma2(pp0, v0.p[1], o0[1]);  o1[1] = fma2(pp1, v0.p[1], o1[1]);
        o0[2] = fma2(pp0, v1.p[0], o0[2]);  o1[2] = fma2(pp1, v1.p[0], o1[2]);
        o0[3] = fma2(pp0, v1.p[1], o0[3]);  o1[3] = fma2(pp1, v1.p[1], o1[3]);
        o0[4] = fma2(pp0, v2.p[0], o0[4]);  o1[4] = fma2(pp1, v2.p[0], o1[4]);
        o0[5] = fma2(pp0, v2.p[1], o0[5]);  o1[5] = fma2(pp1, v2.p[1], o1[5]);
        o0[6] = fma2(pp0, v3.p[0], o0[6]);  o1[6] = fma2(pp1, v3.p[0], o1[6]);
        o0[7] = fma2(pp0, v3.p[1], o0[7]);  o1[7] = fma2(pp1, v3.p[1], o1[7]);
    }

    {   // ---- keys 1..250: merged main + pick (QA) ----
        u64 qe0[8], qe1[8];
        const u64* p0 = (const u64*)(g_QA + qi0);
        const u64* p1 = (const u64*)(g_QA + qi1);
#pragma unroll
        for (int j = 0; j < 8; j++) { qe0[j] = z0 ? 0ull : p0[j]; qe1[j] = p1[j]; }
        attn_scan_merged(qm0, qm1, qe0, qe1, Ks + 1*4, Vs + 1*4, NPICK,
                         l0, l1, o0, o1);
    }
    {   // ---- keys 251..500: merged main + delivery (QB) ----
        u64 qe0[8], qe1[8];
        const u64* p0 = (const u64*)(g_QB + qi0);
        const u64* p1 = (const u64*)(g_QB + qi1);
#pragma unroll
        for (int j = 0; j < 8; j++) { qe0[j] = z0 ? 0ull : p0[j]; qe1[j] = p1[j]; }
        attn_scan_merged(qm0, qm1, qe0, qe1, Ks + (1+NPICK)*4, Vs + (1+NPICK)*4,
                         NDEL, l0, l1, o0, o1);
    }

    // token-major writes: g_heads3[b*Gg + row][h*16 + v]  (4x STG.128)
    {
        const u64 iv0 = dup2(1.f / l0);
        u64* hp = (u64*)(g_heads3 + (size_t)(b*Gg + r0)*128 + h*16);
#pragma unroll
        for (int j = 0; j < 8; j++) hp[j] = mul2(o0[j], iv0);
    }
    if (has1) {
        const u64 iv1 = dup2(1.f / l1);
        u64* hp = (u64*)(g_heads3 + (size_t)(b*Gg + r1)*128 + h*16);
#pragma unroll
        for (int j = 0; j < 8; j++) hp[j] = mul2(o1[j], iv1);
    }
}

// ==========================================================================
// Kernel 3: out[token][e] = sum_hv heads3[token][hv] * W_out[hv][e]
// Round-13 config (best measured: 15.1us).  126 blocks x 256 threads.
// ==========================================================================
#define OT_GT  64
#define W_PAD  130
#define K3_SMEM ((128*W_PAD + OT_GT*128)*4)   // 99328 B

__global__ void __launch_bounds__(256) out_kernel(const float* __restrict__ Wo,
                                                  float* __restrict__ out)
{
    extern __shared__ float sm[];
    float* Bs = sm;                  // 128 x 130 (W_out, padded rows)
    float* As = sm + 128*W_PAD;      // 64 tokens x 128 hv (token-major)

    const int t0  = blockIdx.x * OT_GT;
    const int tid = threadIdx.x;

    {   // stage W_out: 128x128, rows padded to 130
        const float2* src = (const float2*)Wo;
        for (int i = tid; i < 128*64; i += 256) {
            int r = i >> 6, c = i & 63;
            *(float2*)(Bs + r*W_PAD + 2*c) = src[i];
        }
    }
    {   // stage A tile: heads3[t0..t0+63][0..127]  (coalesced float4)
        const float4* src = (const float4*)(g_heads3 + (size_t)t0*128);
        float4* dst = (float4*)As;
#pragma unroll
        for (int i = 0; i < 8; i++) dst[tid + i*256] = src[tid + i*256];
    }
    __syncthreads();

    const int elane = tid & 15;      // 8 e-cols as u64 pairs: col = elane+16j
    const int grow  = tid >> 4;      // 16 grows x 4 tokens each

    u64 acc[4][4];
#pragma unroll
    for (int gg = 0; gg < 4; gg++)
#pragma unroll
        for (int j = 0; j < 4; j++) acc[gg][j] = 0ull;

    const float* Ap = As + grow*4*128;           // 4 token rows of 128
    const u64*   Bp = (const u64*)Bs + elane;    // row stride 65 u64

#pragma unroll 4
    for (int hv = 0; hv < 128; hv++) {
        float a0 = Ap[hv];
        float a1 = Ap[hv + 128];
        float a2 = Ap[hv + 256];
        float a3 = Ap[hv + 384];
        u64 b0 = Bp[hv*65];
        u64 b1 = Bp[hv*65 + 16];
        u64 b2 = Bp[hv*65 + 32];
        u64 b3 = Bp[hv*65 + 48];
        u64 aa0 = dup2(a0), aa1 = dup2(a1), aa2 = dup2(a2), aa3 = dup2(a3);
        acc[0][0] = fma2(b0, aa0, acc[0][0]);
        acc[1][0] = fma2(b0, aa1, acc[1][0]);
        acc[2][0] = fma2(b0, aa2, acc[2][0]);
        acc[3][0] = fma2(b0, aa3, acc[3][0]);
        acc[0][1] = fma2(b1, aa0, acc[0][1]);
        acc[1][1] = fma2(b1, aa1, acc[1][1]);
        acc[2][1] = fma2(b1, aa2, acc[2][1]);
        acc[3][1] = fma2(b1, aa3, acc[3][1]);
        acc[0][2] = fma2(b2, aa0, acc[0][2]);
        acc[1][2] = fma2(b2, aa1, acc[1][2]);
        acc[2][2] = fma2(b2, aa2, acc[2][2]);
        acc[3][2] = fma2(b2, aa3, acc[3][2]);
        acc[0][3] = fma2(b3, aa0, acc[0][3]);
        acc[1][3] = fma2(b3, aa1, acc[1][3]);
        acc[2][3] = fma2(b3, aa2, acc[2][3]);
        acc[3][3] = fma2(b3, aa3, acc[3][3]);
    }

#pragma unroll
    for (int gg = 0; gg < 4; gg++) {
        const int token = t0 + grow*4 + gg;
        if (token < NTOK) {
            float* op = out + (size_t)token*Ee;
#pragma unroll
            for (int j = 0; j < 4; j++) {
                float x, y; upk(acc[gg][j], x, y);
                *(float2*)(op + 2*(elane + 16*j)) = make_float2(x, y);
            }
        }
    }
}

// ==========================================================================
extern "C" void kernel_launch(void* const* d_in, const int* in_sizes, int n_in,
                              void* d_out, int out_size)
{
    const float* q  = (const float*)d_in[0];
    const float* Wq = (const float*)d_in[1];
    const float* Wk = (const float*)d_in[2];
    const float* Wv = (const float*)d_in[3];
    const float* W1 = (const float*)d_in[4];
    const float* W2 = (const float*)d_in[5];
    const float* W3 = (const float*)d_in[6];
    const float* W4 = (const float*)d_in[7];
    const float* Wo = (const float*)d_in[8];
    float* out = (float*)d_out;

    cudaFuncSetAttribute(proj_kernel, cudaFuncAttributeMaxDynamicSharedMemorySize, K1_SMEM);
    cudaFuncSetAttribute(attn_kernel, cudaFuncAttributeMaxDynamicSharedMemorySize, K2_SMEM);
    cudaFuncSetAttribute(out_kernel,  cudaFuncAttributeMaxDynamicSharedMemorySize, K3_SMEM);

    dim3 g0(7, Hh);
    wprep_kernel<<<g0, 256>>>(Wq, Wk, Wv, W1, W2, W3, W4);

    dim3 g1((NTOK + PT_TOK - 1)/PT_TOK, Hh);        // (126, 8)
    proj_kernel<<<g1, 256, K1_SMEM>>>(q);

    dim3 g2(Bb, Hh);                                // 128 blocks x 256 threads
    attn_kernel<<<g2, 256, K2_SMEM>>>();

    out_kernel<<<NTOKP/OT_GT, 256, K3_SMEM>>>(Wo, out);   // 126 blocks
}